// round 4
// baseline (speedup 1.0000x reference)
#include <cuda_runtime.h>

// ---------------------------------------------------------------------------
// CML2DWithStats: 15 steps of
//   mapped  = 3.9*g*(1-g)
//   local   = depthwise_conv3x3(mapped, K)            (zero padding)
//   g       = clamp(0.85*(0.7*mapped + 0.3*local) + 0.15*drive, 1e-4, 1-1e-4)
// Outputs (concatenated, each [16,8,256,256] f32):
//   last, mean_t(states), var_t(states), last-drive, last-drive
//
// Fused temporal-blocking kernel: one CTA per (batch*chan, 32-row band).
// smem window: 64 rows x 264 cols, double buffered (135 KB, 1 CTA/SM).
// Image row y maps to smem row r = y - y0 + 16. Step s computes smem rows
// [s+1, 62-s] (shrinking cone); step 15 is exactly the interior [16,47].
// Affine stages folded: g = sum(W .* mapped_nbr) + 0.15*drive,
// W = 0.255*K with +0.595 added at the center tap.
// Zero-initialized smem + never writing out-of-image rows implements the
// conv's zero padding exactly.
// ---------------------------------------------------------------------------

#define SSTR  264                      // smem row stride (floats), x stored at col x+4
#define SROWS 64
#define NBUF  (SROWS * SSTR)           // 16896 floats per buffer
#define PL    8388608L                 // elements per output plane (16*8*256*256)

// Load mapped[x0-1 .. x0+4] for one smem row: one LDS.128 + 2 shuffles.
// Warp lanes cover contiguous x groups (x0 = 4*tx, tx contiguous per warp),
// so lane l's left neighbor is lane l-1's v.w. Edge lanes load scalars.
__device__ __forceinline__ void load6(const float* __restrict__ p, int lane, float m[6]) {
    float4 v = *reinterpret_cast<const float4*>(p);
    float left  = __shfl_up_sync(0xffffffffu, v.w, 1);
    float right = __shfl_down_sync(0xffffffffu, v.x, 1);
    if (lane == 0)  left  = p[-1];
    if (lane == 31) right = p[4];
    m[0] = left; m[1] = v.x; m[2] = v.y; m[3] = v.z; m[4] = v.w; m[5] = right;
}

template<bool LAST>
__device__ __forceinline__ void do_step(
    const float* __restrict__ src, float* __restrict__ dst,
    int rlo, int rhi, int ty, int lane, int x0, int y0,
    const float* __restrict__ dpl, const float* __restrict__ W,
    float (&sum)[4][4], float (&sq)[4][4],
    float* __restrict__ outBase)
{
    #pragma unroll
    for (int k = 0; k < 8; ++k) {
        const int r = ty + 8 * k;                 // absolute row ownership
        const int y = y0 - 16 + r;
        // Warp-uniform predicate (depends only on ty); shuffles below stay safe.
        if (r < rlo || r > rhi || y < 0 || y > 255) continue;

        const float* p = src + r * SSTR + 4 + x0;
        float A[6], B[6], C[6];
        load6(p - SSTR, lane, A);
        load6(p,        lane, B);
        load6(p + SSTR, lane, C);

        const float4 d4 = *reinterpret_cast<const float4*>(dpl + y * 256 + x0);
        const float dd[4] = {d4.x, d4.y, d4.z, d4.w};

        float g[4];
        #pragma unroll
        for (int j = 0; j < 4; ++j) {
            float t =      W[0] * A[j];
            t = fmaf(W[1], A[j + 1], t);
            t = fmaf(W[2], A[j + 2], t);
            t = fmaf(W[3], B[j],     t);
            t = fmaf(W[4], B[j + 1], t);
            t = fmaf(W[5], B[j + 2], t);
            t = fmaf(W[6], C[j],     t);
            t = fmaf(W[7], C[j + 1], t);
            t = fmaf(W[8], C[j + 2], t);
            t = fmaf(0.15f, dd[j],   t);
            g[j] = fminf(fmaxf(t, 1e-4f), 1.0f - 1e-4f);
        }

        if (k >= 2 && k <= 5) {                   // interior row: accumulate stats
            #pragma unroll
            for (int j = 0; j < 4; ++j) {
                sum[k - 2][j] += g[j];
                sq[k - 2][j]   = fmaf(g[j], g[j], sq[k - 2][j]);
            }
        }

        if (!LAST) {
            // next step's input: mapped = 3.9*g*(1-g)
            float4 m;
            m.x = (3.9f * g[0]) * (1.0f - g[0]);
            m.y = (3.9f * g[1]) * (1.0f - g[1]);
            m.z = (3.9f * g[2]) * (1.0f - g[2]);
            m.w = (3.9f * g[3]) * (1.0f - g[3]);
            *reinterpret_cast<float4*>(dst + r * SSTR + 4 + x0) = m;
        } else {
            // last step: cone == interior; write last / delta / last_drive
            const long o = (long)y * 256 + x0;
            *reinterpret_cast<float4*>(outBase + o) =
                make_float4(g[0], g[1], g[2], g[3]);
            const float4 dl = make_float4(g[0] - dd[0], g[1] - dd[1],
                                          g[2] - dd[2], g[3] - dd[3]);
            *reinterpret_cast<float4*>(outBase + 3L * PL + o) = dl;
            *reinterpret_cast<float4*>(outBase + 4L * PL + o) = dl;
        }
    }
}

__global__ void __launch_bounds__(512, 1)
cml_fused_kernel(const float* __restrict__ drive,
                 const float* __restrict__ Kl,
                 float* __restrict__ out)
{
    extern __shared__ float smem[];
    float* buf0 = smem;
    float* buf1 = smem + NBUF;

    const int tile = blockIdx.x;          // (b*8 + c)*8 + band
    const int band = tile & 7;
    const int bc   = tile >> 3;
    const int ch   = bc & 7;
    const int y0   = band * 32;           // first interior image row
    const float* dpl      = drive + (long)bc * 65536L;
    float*       outBase  = out   + (long)bc * 65536L;

    const int tid  = threadIdx.x;
    const int tx   = tid & 63;            // x group (4 columns each)
    const int ty   = tid >> 6;            // 0..7 (uniform within each warp)
    const int lane = tid & 31;
    const int x0   = tx << 2;

    // Folded conv weights.
    float W[9];
    #pragma unroll
    for (int i = 0; i < 9; ++i) W[i] = 0.255f * __ldg(&Kl[ch * 9 + i]);
    W[4] += 0.595f;

    // Zero both buffers: pad columns, guard rows and out-of-image rows stay 0
    // forever -> exact zero padding for the conv.
    for (int i = tid; i < 2 * NBUF; i += 512) smem[i] = 0.0f;
    __syncthreads();

    // Init buffer 0 with mapped(drive) on rows r = 1..62 (image rows in range).
    for (int idx = tid; idx < 62 * 64; idx += 512) {
        const int r  = 1 + (idx >> 6);
        const int xg = idx & 63;
        const int y  = y0 - 16 + r;
        if (y >= 0 && y < 256) {
            const float4 d = *reinterpret_cast<const float4*>(dpl + y * 256 + xg * 4);
            float4 m;
            m.x = (3.9f * d.x) * (1.0f - d.x);
            m.y = (3.9f * d.y) * (1.0f - d.y);
            m.z = (3.9f * d.z) * (1.0f - d.z);
            m.w = (3.9f * d.w) * (1.0f - d.w);
            *reinterpret_cast<float4*>(buf0 + r * SSTR + 4 + xg * 4) = m;
        }
    }
    __syncthreads();

    float sum[4][4], sq[4][4];
    #pragma unroll
    for (int k = 0; k < 4; ++k)
        #pragma unroll
        for (int j = 0; j < 4; ++j) { sum[k][j] = 0.0f; sq[k][j] = 0.0f; }

    const float* src = buf0;
    float*       dst = buf1;
    for (int s = 1; s <= 14; ++s) {
        do_step<false>(src, dst, s + 1, 62 - s, ty, lane, x0, y0,
                       dpl, W, sum, sq, outBase);
        const float* t = src; src = dst; dst = const_cast<float*>(t);
        __syncthreads();
    }
    do_step<true>(src, dst, 16, 47, ty, lane, x0, y0,
                  dpl, W, sum, sq, outBase);

    // mean / var from register accumulators. Interior row for (ty, k):
    // r = ty + 8*(k+2)  ->  y = y0 + ty + 8*k.
    const float inv15 = 1.0f / 15.0f;
    #pragma unroll
    for (int k = 0; k < 4; ++k) {
        const int y = y0 + ty + 8 * k;
        const long o = (long)y * 256 + x0;
        float4 mn, vr;
        mn.x = sum[k][0] * inv15;
        mn.y = sum[k][1] * inv15;
        mn.z = sum[k][2] * inv15;
        mn.w = sum[k][3] * inv15;
        vr.x = fmaf(-mn.x, mn.x, sq[k][0] * inv15);
        vr.y = fmaf(-mn.y, mn.y, sq[k][1] * inv15);
        vr.z = fmaf(-mn.z, mn.z, sq[k][2] * inv15);
        vr.w = fmaf(-mn.w, mn.w, sq[k][3] * inv15);
        *reinterpret_cast<float4*>(outBase + 1L * PL + o) = mn;
        *reinterpret_cast<float4*>(outBase + 2L * PL + o) = vr;
    }
}

extern "C" void kernel_launch(void* const* d_in, const int* in_sizes, int n_in,
                              void* d_out, int out_size)
{
    const float* drive = (const float*)d_in[0];
    const float* Kl    = (const float*)d_in[1];
    // Defensive: metadata order should be (drive, K_local); swap if reversed.
    if (n_in >= 2 && in_sizes[0] == 72) {
        const float* t = drive; drive = Kl; Kl = t;
    }
    float* out = (float*)d_out;
    (void)out_size;

    const size_t shmem = 2 * NBUF * sizeof(float);   // 135168 bytes
    cudaFuncSetAttribute(cml_fused_kernel,
                         cudaFuncAttributeMaxDynamicSharedMemorySize, (int)shmem);
    cml_fused_kernel<<<1024, 512, shmem>>>(drive, Kl, out);
}

// round 6
// speedup vs baseline: 1.4823x; 1.4823x over previous
#include <cuda_runtime.h>

// ---------------------------------------------------------------------------
// CML2DWithStats, fused temporal-blocking kernel (Round 5 resubmit).
// One CTA per (batch*chan, 32-row band). smem window: 66 logical rows
// (-1..64, guards included) x 264 cols, double buffered (139 KB, 1 CTA/SM).
// Image row y <-> logical smem row r = y - y0 + 16 (stored at physical r+1).
// Step s computes rows [s+1, 62-s]; step 15 == interior [16,47].
//
// vs Round-4 (L1-bound, 56.8%): contiguous-quad row ownership with register
// rolling (C window of row i becomes B of row i+1): 6 load6 per 4 rows
// instead of 12; interior block (rows [16,47], always in-cone) is
// unconditional and keeps its drive values in registers for all 15 steps.
// ---------------------------------------------------------------------------

#define SSTR  264                      // smem row stride (floats)
#define LROWS 66                       // logical rows -1..64 (physical 0..65)
#define NBUF  (LROWS * SSTR)           // 17424 floats per buffer
#define PL    8388608L                 // elements per output plane

// mapped[x0-1 .. x0+4] for one row: one LDS.128 + 2 shuffles; edge lanes
// read the in-row halo columns (cols x-1 / x+4 exist: 4-col pads per side).
__device__ __forceinline__ void load6(const float* __restrict__ p, int lane, float m[6]) {
    float4 v = *reinterpret_cast<const float4*>(p);
    float left  = __shfl_up_sync(0xffffffffu, v.w, 1);
    float right = __shfl_down_sync(0xffffffffu, v.x, 1);
    if (lane == 0)  left  = p[-1];
    if (lane == 31) right = p[4];
    m[0] = left; m[1] = v.x; m[2] = v.y; m[3] = v.z; m[4] = v.w; m[5] = right;
}

// Folded update: g = sum(W .* mapped_nbr) + 0.15*drive, clamped.
__device__ __forceinline__ void taps(const float* __restrict__ W,
                                     const float A[6], const float B[6],
                                     const float C[6], const float dd[4],
                                     float g[4]) {
    #pragma unroll
    for (int j = 0; j < 4; ++j) {
        float t =      W[0] * A[j];
        t = fmaf(W[1], A[j + 1], t);
        t = fmaf(W[2], A[j + 2], t);
        t = fmaf(W[3], B[j],     t);
        t = fmaf(W[4], B[j + 1], t);
        t = fmaf(W[5], B[j + 2], t);
        t = fmaf(W[6], C[j],     t);
        t = fmaf(W[7], C[j + 1], t);
        t = fmaf(W[8], C[j + 2], t);
        t = fmaf(0.15f, dd[j],   t);
        g[j] = fminf(fmaxf(t, 1e-4f), 1.0f - 1e-4f);
    }
}

// Halo block: 4 contiguous rows starting at R0, predicated by cone + image.
// srcb/dstb point at logical row 0 (physical row 1). Predicates are
// warp-uniform (depend on ty-derived R0 and uniform lo/hi/y0). Stale-row
// reads are safe: computed rows' windows lie inside [lo-1,hi+1], exactly
// what the previous step produced; stale data only feeds discarded rows.
__device__ __forceinline__ void halo_block(
    const float* __restrict__ srcb, float* __restrict__ dstb,
    int R0, int lo, int hi, int lane, int x0, int y0,
    const float* __restrict__ dpl, const float* __restrict__ W)
{
    if (R0 > hi || R0 + 3 < lo) return;
    const int yb = y0 - 16 + R0;
    if (yb + 3 < 0 || yb > 255) return;

    const float* pA = srcb + (R0 - 1) * SSTR + 4 + x0;
    float A[6], B[6], C[6];
    load6(pA,        lane, A);
    load6(pA + SSTR, lane, B);
    #pragma unroll
    for (int i = 0; i < 4; ++i) {
        load6(pA + (i + 2) * SSTR, lane, C);
        const int r = R0 + i;
        const int y = yb + i;
        if (r >= lo && r <= hi && y >= 0 && y <= 255) {
            const float4 d4 = *reinterpret_cast<const float4*>(dpl + y * 256 + x0);
            const float dd[4] = {d4.x, d4.y, d4.z, d4.w};
            float g[4];
            taps(W, A, B, C, dd, g);
            float4 mv;
            mv.x = (3.9f * g[0]) * (1.0f - g[0]);
            mv.y = (3.9f * g[1]) * (1.0f - g[1]);
            mv.z = (3.9f * g[2]) * (1.0f - g[2]);
            mv.w = (3.9f * g[3]) * (1.0f - g[3]);
            *reinterpret_cast<float4*>(dstb + r * SSTR + 4 + x0) = mv;
        }
        #pragma unroll
        for (int q = 0; q < 6; ++q) { A[q] = B[q]; B[q] = C[q]; }
    }
}

// Interior block: rows [R0, R0+3] subset of [16,47]; inside the cone at every
// step -> unconditional. Drive values come from registers (ddreg).
template<bool LAST>
__device__ __forceinline__ void int_block(
    const float* __restrict__ srcb, float* __restrict__ dstb,
    int R0, int lane, int x0, int y0,
    const float (&ddreg)[4][4], const float* __restrict__ W,
    float (&sum)[4][4], float (&sq)[4][4], float* __restrict__ outBase)
{
    const float* pA = srcb + (R0 - 1) * SSTR + 4 + x0;
    float A[6], B[6], C[6];
    load6(pA,        lane, A);
    load6(pA + SSTR, lane, B);
    #pragma unroll
    for (int i = 0; i < 4; ++i) {
        load6(pA + (i + 2) * SSTR, lane, C);
        float g[4];
        taps(W, A, B, C, ddreg[i], g);
        #pragma unroll
        for (int j = 0; j < 4; ++j) {
            sum[i][j] += g[j];
            sq[i][j]   = fmaf(g[j], g[j], sq[i][j]);
        }
        if (!LAST) {
            float4 mv;
            mv.x = (3.9f * g[0]) * (1.0f - g[0]);
            mv.y = (3.9f * g[1]) * (1.0f - g[1]);
            mv.z = (3.9f * g[2]) * (1.0f - g[2]);
            mv.w = (3.9f * g[3]) * (1.0f - g[3]);
            *reinterpret_cast<float4*>(dstb + (R0 + i) * SSTR + 4 + x0) = mv;
        } else {
            const int y = y0 + (R0 - 16) + i;
            const long o = (long)y * 256 + x0;
            *reinterpret_cast<float4*>(outBase + o) =
                make_float4(g[0], g[1], g[2], g[3]);
            const float4 dl = make_float4(g[0] - ddreg[i][0], g[1] - ddreg[i][1],
                                          g[2] - ddreg[i][2], g[3] - ddreg[i][3]);
            *reinterpret_cast<float4*>(outBase + 3L * PL + o) = dl;
            *reinterpret_cast<float4*>(outBase + 4L * PL + o) = dl;
        }
        #pragma unroll
        for (int q = 0; q < 6; ++q) { A[q] = B[q]; B[q] = C[q]; }
    }
}

__global__ void __launch_bounds__(512, 1)
cml_fused_kernel(const float* __restrict__ drive,
                 const float* __restrict__ Kl,
                 float* __restrict__ out)
{
    extern __shared__ float smem[];
    float* b0 = smem + SSTR;           // logical row 0 of buffer 0
    float* b1 = smem + NBUF + SSTR;    // logical row 0 of buffer 1

    const int tile = blockIdx.x;       // (b*8 + c)*8 + band
    const int band = tile & 7;
    const int bc   = tile >> 3;
    const int ch   = bc & 7;
    const int y0   = band * 32;
    const float* dpl     = drive + (long)bc * 65536L;
    float*       outBase = out   + (long)bc * 65536L;

    const int tid  = threadIdx.x;
    const int tx   = tid & 63;         // x group (4 columns)
    const int ty   = tid >> 6;         // 0..7, warp-uniform
    const int lane = tid & 31;
    const int x0   = tx << 2;

    // Block ownership (contiguous quads, balance-preserving interleave):
    //   interior block Ri subset of [16,47]; halo block Rh in [0,15]/[48,63].
    const int Ri = (ty < 4) ? (32 + 4 * ty) : (16 + 4 * (ty - 4));
    const int Rh = (ty < 4) ? (4 * ty)      : (48 + 4 * (ty - 4));

    // Folded conv weights: W = 0.255*K, +0.595 at center.
    float W[9];
    #pragma unroll
    for (int i = 0; i < 9; ++i) W[i] = 0.255f * __ldg(&Kl[ch * 9 + i]);
    W[4] += 0.595f;

    // Interior drive values live in registers for all 15 steps.
    float ddreg[4][4];
    #pragma unroll
    for (int i = 0; i < 4; ++i) {
        const int y = y0 + (Ri - 16) + i;
        const float4 d4 = *reinterpret_cast<const float4*>(dpl + y * 256 + x0);
        ddreg[i][0] = d4.x; ddreg[i][1] = d4.y;
        ddreg[i][2] = d4.z; ddreg[i][3] = d4.w;
    }

    // Zero both buffers: guards + out-of-image rows stay 0 forever,
    // implementing the conv's zero padding exactly.
    for (int i = tid; i < 2 * NBUF; i += 512) smem[i] = 0.0f;
    __syncthreads();

    // Init buffer 0 with mapped(drive) on logical rows 1..62 (valid y only).
    for (int idx = tid; idx < 62 * 64; idx += 512) {
        const int r  = 1 + (idx >> 6);
        const int xg = (idx & 63) << 2;
        const int y  = y0 - 16 + r;
        if (y >= 0 && y < 256) {
            const float4 d = *reinterpret_cast<const float4*>(dpl + y * 256 + xg);
            float4 m;
            m.x = (3.9f * d.x) * (1.0f - d.x);
            m.y = (3.9f * d.y) * (1.0f - d.y);
            m.z = (3.9f * d.z) * (1.0f - d.z);
            m.w = (3.9f * d.w) * (1.0f - d.w);
            *reinterpret_cast<float4*>(b0 + r * SSTR + 4 + xg) = m;
        }
    }
    __syncthreads();

    float sum[4][4], sq[4][4];
    #pragma unroll
    for (int i = 0; i < 4; ++i)
        #pragma unroll
        for (int j = 0; j < 4; ++j) { sum[i][j] = 0.0f; sq[i][j] = 0.0f; }

    const float* src = b0;
    float*       dst = b1;
    for (int s = 1; s <= 14; ++s) {
        const int lo = s + 1, hi = 62 - s;
        halo_block(src, dst, Rh, lo, hi, lane, x0, y0, dpl, W);
        int_block<false>(src, dst, Ri, lane, x0, y0, ddreg, W, sum, sq, outBase);
        const float* t = src; src = dst; dst = const_cast<float*>(t);
        __syncthreads();
    }
    // Step 15: cone == interior; halo block is fully outside -> skipped.
    int_block<true>(src, dst, Ri, lane, x0, y0, ddreg, W, sum, sq, outBase);

    // mean / var from register accumulators.
    const float inv15 = 1.0f / 15.0f;
    #pragma unroll
    for (int i = 0; i < 4; ++i) {
        const int y = y0 + (Ri - 16) + i;
        const long o = (long)y * 256 + x0;
        float4 mn, vr;
        mn.x = sum[i][0] * inv15;
        mn.y = sum[i][1] * inv15;
        mn.z = sum[i][2] * inv15;
        mn.w = sum[i][3] * inv15;
        vr.x = fmaf(-mn.x, mn.x, sq[i][0] * inv15);
        vr.y = fmaf(-mn.y, mn.y, sq[i][1] * inv15);
        vr.z = fmaf(-mn.z, mn.z, sq[i][2] * inv15);
        vr.w = fmaf(-mn.w, mn.w, sq[i][3] * inv15);
        *reinterpret_cast<float4*>(outBase + 1L * PL + o) = mn;
        *reinterpret_cast<float4*>(outBase + 2L * PL + o) = vr;
    }
}

extern "C" void kernel_launch(void* const* d_in, const int* in_sizes, int n_in,
                              void* d_out, int out_size)
{
    const float* drive = (const float*)d_in[0];
    const float* Kl    = (const float*)d_in[1];
    if (n_in >= 2 && in_sizes[0] == 72) {         // defensive input-order check
        const float* t = drive; drive = Kl; Kl = t;
    }
    float* out = (float*)d_out;
    (void)out_size;

    const size_t shmem = 2 * NBUF * sizeof(float);   // 139392 bytes
    cudaFuncSetAttribute(cml_fused_kernel,
                         cudaFuncAttributeMaxDynamicSharedMemorySize, (int)shmem);
    cml_fused_kernel<<<1024, 512, shmem>>>(drive, Kl, out);
}